// round 2
// baseline (speedup 1.0000x reference)
#include <cuda_runtime.h>

#define N_   16384
#define D_   2048
#define P_   256
#define NB   32
#define NL   100
#define NSEG (NB*NL)

// ---------------- scratch (device globals; no allocations allowed) ----------
__device__ float g_sum_bl[NSEG * D_];   // per-(batch,label) column sums   26.2MB
__device__ float g_sum_b [NB   * D_];   // per-batch column sums
__device__ float g_cnt_bl[NSEG];        // per-(batch,label) counts
__device__ float g_inv   [NSEG];        // 1/diff_cnt (0 if diff_cnt<=0)
__device__ float g_M     [NSEG * P_];   // mean_seg @ W2^T + b1 + b2
__device__ int   g_seg   [N_];          // combined segment id per row
__device__ int   g_bstart[NB + 1];      // batch row offsets (label_batch sorted)
__device__ int   g_is64;                // bit0: label is int64, bit1: label_batch is int64

// ---------------- dtype detection + count zeroing ---------------------------
__global__ void k_detect(const int* label, const int* lb) {
    __shared__ int nz_la, nz_lb;
    int t = threadIdx.x;
    if (t == 0) { nz_la = 0; nz_lb = 0; }
    __syncthreads();
    if (t < 64) {
        // odd 32-bit word of element (t*128): zero for int64 data, a real
        // (mostly nonzero) value for int32 data at spread positions.
        int w = 2 * (t * 128) + 1;
        if (label[w] != 0) atomicOr(&nz_la, 1);
        if (lb[w]    != 0) atomicOr(&nz_lb, 1);
    }
    __syncthreads();
    if (t == 0) g_is64 = (nz_la ? 0 : 1) | (nz_lb ? 0 : 2);
    for (int i = t; i < NSEG; i += blockDim.x) g_cnt_bl[i] = 0.0f;
}

__device__ __forceinline__ int ld_idx(const int* p, int i, bool is64) {
    return is64 ? p[2 * i] : p[i];   // little-endian low word
}

// ---------------- seg ids, counts, batch boundaries --------------------------
__global__ void k_prep(const int* label, const int* lb) {
    bool la64 = (g_is64 & 1) != 0, lb64 = (g_is64 & 2) != 0;
    int i = blockIdx.x * blockDim.x + threadIdx.x;
    if (i < N_) {
        int la = ld_idx(label, i, la64);
        int b  = ld_idx(lb,    i, lb64);
        int s  = b * NL + la;
        g_seg[i] = s;
        atomicAdd(&g_cnt_bl[s], 1.0f);
    }
    if (blockIdx.x == 0 && threadIdx.x <= NB) {
        int target = threadIdx.x;
        int lo = 0, hi = N_;
        while (lo < hi) {
            int mid = (lo + hi) >> 1;
            if (ld_idx(lb, mid, lb64) < target) lo = mid + 1; else hi = mid;
        }
        g_bstart[target] = lo;
    }
}

// ---------------- segment sums: grid (D_/64 chunks, NB batches) --------------
__global__ void k_segsum(const float* __restrict__ x) {
    __shared__ float acc[NL * 64];      // 25.6 KB
    int b  = blockIdx.y;
    int c0 = blockIdx.x * 64;
    int t  = threadIdx.x;
    for (int i = t; i < NL * 64; i += 256) acc[i] = 0.0f;
    __syncthreads();
    int r0 = g_bstart[b], r1 = g_bstart[b + 1];
    int col = t & 63, rs = t >> 6;
    for (int r = r0 + rs; r < r1; r += 4) {
        int lab = g_seg[r] - b * NL;
        atomicAdd(&acc[lab * 64 + col], x[(size_t)r * D_ + c0 + col]);
    }
    __syncthreads();
    for (int i = t; i < NL * 64; i += 256) {
        int l = i >> 6, c = i & 63;
        g_sum_bl[(size_t)(b * NL + l) * D_ + c0 + c] = acc[i];
    }
    if (t < 64) {
        float s = 0.0f;
        #pragma unroll
        for (int l = 0; l < NL; l++) s += acc[l * 64 + t];
        g_sum_b[(size_t)b * D_ + c0 + t] = s;
    }
}

// ---------------- per-segment 1/diff_cnt -------------------------------------
__global__ void k_inv() {
    int s = blockIdx.x * blockDim.x + threadIdx.x;
    if (s < NSEG) {
        int b = s / NL;
        float cb = (float)(g_bstart[b + 1] - g_bstart[b]);
        float d  = cb - g_cnt_bl[s];
        g_inv[s] = (d > 0.5f) ? (1.0f / d) : 0.0f;
    }
}

// ---------------- GEMM 1: M[3200,256] = mean_seg @ W2^T + (b1+b2) -----------
// 64x64 block tile, BK=16, 256 threads, 4x4 per thread.
__global__ void k_gemm_mean(const float* __restrict__ W2,
                            const float* __restrict__ b1,
                            const float* __restrict__ b2) {
    __shared__ __align__(16) float As[16][64];
    __shared__ __align__(16) float Bs[16][64];
    int m0 = blockIdx.y * 64, n0 = blockIdx.x * 64;
    int t  = threadIdx.x;
    int lr = t >> 2;            // load row 0..63
    int lk = (t & 3) * 4;       // k offset within tile
    int tx = t & 15, ty = t >> 4;
    float acc[4][4] = {};

    int   sA  = m0 + lr;
    int   bA  = sA / NL;
    float inv = g_inv[sA];
    const float* pSb  = g_sum_b  + (size_t)bA * D_ + lk;
    const float* pSbl = g_sum_bl + (size_t)sA * D_ + lk;
    const float* pB   = W2       + (size_t)(n0 + lr) * D_ + lk;

    for (int k0 = 0; k0 < D_; k0 += 16) {
        float4 s1 = *(const float4*)(pSb  + k0);
        float4 s2 = *(const float4*)(pSbl + k0);
        As[lk + 0][lr] = (s1.x - s2.x) * inv;
        As[lk + 1][lr] = (s1.y - s2.y) * inv;
        As[lk + 2][lr] = (s1.z - s2.z) * inv;
        As[lk + 3][lr] = (s1.w - s2.w) * inv;
        float4 bb = *(const float4*)(pB + k0);
        Bs[lk + 0][lr] = bb.x;
        Bs[lk + 1][lr] = bb.y;
        Bs[lk + 2][lr] = bb.z;
        Bs[lk + 3][lr] = bb.w;
        __syncthreads();
        #pragma unroll
        for (int kk = 0; kk < 16; kk++) {
            float4 av = *(const float4*)(&As[kk][ty * 4]);
            float4 bv = *(const float4*)(&Bs[kk][tx * 4]);
            float a[4] = {av.x, av.y, av.z, av.w};
            float b[4] = {bv.x, bv.y, bv.z, bv.w};
            #pragma unroll
            for (int i = 0; i < 4; i++)
                #pragma unroll
                for (int j = 0; j < 4; j++)
                    acc[i][j] += a[i] * b[j];
        }
        __syncthreads();
    }
    #pragma unroll
    for (int i = 0; i < 4; i++) {
        int s = m0 + ty * 4 + i;
        #pragma unroll
        for (int j = 0; j < 4; j++) {
            int p = n0 + tx * 4 + j;
            g_M[(size_t)s * P_ + p] = acc[i][j] + b1[p] + b2[p];
        }
    }
}

// ---------------- GEMM 2: out = x @ W1^T + M[seg] ----------------------------
__global__ void k_gemm_main(const float* __restrict__ x,
                            const float* __restrict__ W1,
                            float* __restrict__ out) {
    __shared__ __align__(16) float As[16][64];
    __shared__ __align__(16) float Bs[16][64];
    int m0 = blockIdx.y * 64, n0 = blockIdx.x * 64;
    int t  = threadIdx.x;
    int lr = t >> 2;
    int lk = (t & 3) * 4;
    int tx = t & 15, ty = t >> 4;
    float acc[4][4] = {};

    const float* pA = x  + (size_t)(m0 + lr) * D_ + lk;
    const float* pB = W1 + (size_t)(n0 + lr) * D_ + lk;

    for (int k0 = 0; k0 < D_; k0 += 16) {
        float4 a4 = *(const float4*)(pA + k0);
        As[lk + 0][lr] = a4.x;
        As[lk + 1][lr] = a4.y;
        As[lk + 2][lr] = a4.z;
        As[lk + 3][lr] = a4.w;
        float4 b4 = *(const float4*)(pB + k0);
        Bs[lk + 0][lr] = b4.x;
        Bs[lk + 1][lr] = b4.y;
        Bs[lk + 2][lr] = b4.z;
        Bs[lk + 3][lr] = b4.w;
        __syncthreads();
        #pragma unroll
        for (int kk = 0; kk < 16; kk++) {
            float4 av = *(const float4*)(&As[kk][ty * 4]);
            float4 bv = *(const float4*)(&Bs[kk][tx * 4]);
            float a[4] = {av.x, av.y, av.z, av.w};
            float b[4] = {bv.x, bv.y, bv.z, bv.w};
            #pragma unroll
            for (int i = 0; i < 4; i++)
                #pragma unroll
                for (int j = 0; j < 4; j++)
                    acc[i][j] += a[i] * b[j];
        }
        __syncthreads();
    }
    #pragma unroll
    for (int i = 0; i < 4; i++) {
        int r = m0 + ty * 4 + i;
        int s = g_seg[r];
        float4 mv = *(const float4*)(&g_M[(size_t)s * P_ + n0 + tx * 4]);
        float4 ov;
        ov.x = acc[i][0] + mv.x;
        ov.y = acc[i][1] + mv.y;
        ov.z = acc[i][2] + mv.z;
        ov.w = acc[i][3] + mv.w;
        *(float4*)(&out[(size_t)r * P_ + n0 + tx * 4]) = ov;
    }
}

// ---------------- launch -----------------------------------------------------
extern "C" void kernel_launch(void* const* d_in, const int* in_sizes, int n_in,
                              void* d_out, int out_size) {
    const float* x     = (const float*)d_in[0];
    const int*   label = (const int*)  d_in[1];
    const int*   lb    = (const int*)  d_in[2];
    const float* W1_w  = (const float*)d_in[3];
    const float* W1_b  = (const float*)d_in[4];
    const float* W2_w  = (const float*)d_in[5];
    const float* W2_b  = (const float*)d_in[6];
    float* out = (float*)d_out;

    k_detect<<<1, 256>>>(label, lb);
    k_prep<<<N_ / 256, 256>>>(label, lb);
    k_segsum<<<dim3(D_ / 64, NB), 256>>>(x);
    k_inv<<<(NSEG + 255) / 256, 256>>>();
    k_gemm_mean<<<dim3(P_ / 64, NSEG / 64), 256>>>(W2_w, W1_b, W2_b);
    k_gemm_main<<<dim3(P_ / 64, N_ / 64), 256>>>(x, W1_w, out);
}

// round 4
// speedup vs baseline: 1.9600x; 1.9600x over previous
#include <cuda_runtime.h>
#include <cuda_bf16.h>
#include <cstdint>

#define N_   16384
#define D_   2048
#define P_   256
#define NB   32
#define NL   100
#define NSEG (NB*NL)
#define KT_TOT 192      // 3 terms * (2048/32) K-tiles of 32
#define NST    4        // pipeline stages

// ---------------- scratch globals (no allocations allowed) -------------------
__device__ __nv_bfloat16 g_xhi[N_ * D_];
__device__ __nv_bfloat16 g_xlo[N_ * D_];
__device__ __nv_bfloat16 g_bhi[512 * D_];   // [W1;W2] hi
__device__ __nv_bfloat16 g_blo[512 * D_];   // [W1;W2] lo
__device__ float g_y2[N_ * P_];             // x @ W2^T
__device__ float g_sum_bl2[NSEG * P_];
__device__ float g_sum_b2 [NB   * P_];
__device__ float g_M[NSEG * P_];
__device__ float g_bias[P_];
__device__ int   g_cnt[NSEG];
__device__ int   g_off[NSEG + 1];
__device__ int   g_cur[NSEG];
__device__ int   g_rows[N_];
__device__ int   g_seg[N_];
__device__ int   g_bstart[NB + 1];
__device__ int   g_is64;

// ---------------- PTX helpers ------------------------------------------------
__device__ __forceinline__ uint32_t smem_u32(const void* p) {
    uint32_t a;
    asm("{ .reg .u64 t; cvta.to.shared.u64 t, %1; cvt.u32.u64 %0, t; }" : "=r"(a) : "l"(p));
    return a;
}
__device__ __forceinline__ void cp16(uint32_t dst, const void* src) {
    asm volatile("cp.async.cg.shared.global [%0], [%1], 16;" :: "r"(dst), "l"(src));
}
#define CP_COMMIT() asm volatile("cp.async.commit_group;" ::: "memory")
#define CP_WAIT2()  asm volatile("cp.async.wait_group 2;"  ::: "memory")
#define CP_WAIT0()  asm volatile("cp.async.wait_group 0;"  ::: "memory")

__device__ __forceinline__ uint32_t swz(uint32_t o) {   // 64B-row swizzle
    return o ^ ((o >> 3) & 0x30);
}
__device__ __forceinline__ void ldm4(uint32_t addr, uint32_t& r0, uint32_t& r1,
                                     uint32_t& r2, uint32_t& r3) {
    asm volatile("ldmatrix.sync.aligned.m8n8.x4.shared.b16 {%0,%1,%2,%3}, [%4];"
                 : "=r"(r0), "=r"(r1), "=r"(r2), "=r"(r3) : "r"(addr));
}
__device__ __forceinline__ void mma16816(float* d, const uint32_t* a,
                                         const uint32_t* b) {
    asm volatile(
        "mma.sync.aligned.m16n8k16.row.col.f32.bf16.bf16.f32 "
        "{%0,%1,%2,%3}, {%4,%5,%6,%7}, {%8,%9}, {%0,%1,%2,%3};"
        : "+f"(d[0]), "+f"(d[1]), "+f"(d[2]), "+f"(d[3])
        : "r"(a[0]), "r"(a[1]), "r"(a[2]), "r"(a[3]), "r"(b[0]), "r"(b[1]));
}

// ---------------- dtype detection + count zeroing ----------------------------
__global__ void k_detect(const int* label, const int* lb) {
    __shared__ int nz_la, nz_lb;
    int t = threadIdx.x;
    if (t == 0) { nz_la = 0; nz_lb = 0; }
    __syncthreads();
    if (t < 64) {
        int w = 2 * (t * 128) + 1;
        if (label[w] != 0) atomicOr(&nz_la, 1);
        if (lb[w]    != 0) atomicOr(&nz_lb, 1);
    }
    __syncthreads();
    if (t == 0) g_is64 = (nz_la ? 0 : 1) | (nz_lb ? 0 : 2);
    for (int i = t; i < NSEG; i += blockDim.x) g_cnt[i] = 0;
}
__device__ __forceinline__ int ld_idx(const int* p, int i, bool is64) {
    return is64 ? p[2 * i] : p[i];
}

// ---------------- seg ids, counts, batch boundaries --------------------------
__global__ void k_prep(const int* label, const int* lb) {
    bool la64 = (g_is64 & 1) != 0, lb64 = (g_is64 & 2) != 0;
    int i = blockIdx.x * blockDim.x + threadIdx.x;
    if (i < N_) {
        int la = ld_idx(label, i, la64);
        int b  = ld_idx(lb,    i, lb64);
        int s  = b * NL + la;
        g_seg[i] = s;
        atomicAdd(&g_cnt[s], 1);
    }
    if (blockIdx.x == 0 && threadIdx.x <= NB) {
        int target = threadIdx.x;
        int lo = 0, hi = N_;
        while (lo < hi) {
            int mid = (lo + hi) >> 1;
            if (ld_idx(lb, mid, lb64) < target) lo = mid + 1; else hi = mid;
        }
        g_bstart[target] = lo;
    }
}

// ---------------- prefix scan over seg counts --------------------------------
__global__ void k_scan() {
    __shared__ int sh[1024];
    int t = threadIdx.x;
    int base = t * 4;
    int c[4];
    #pragma unroll
    for (int i = 0; i < 4; i++) c[i] = (base + i < NSEG) ? g_cnt[base + i] : 0;
    int tot = c[0] + c[1] + c[2] + c[3];
    sh[t] = tot;
    __syncthreads();
    int run = tot;
    for (int d = 1; d < 1024; d <<= 1) {
        int v = (t >= d) ? sh[t - d] : 0;
        __syncthreads();
        run += v; sh[t] = run;
        __syncthreads();
    }
    int excl = (t > 0) ? sh[t - 1] : 0;
    int p = excl;
    #pragma unroll
    for (int i = 0; i < 4; i++) {
        if (base + i <= NSEG) g_off[base + i] = p;
        if (base + i <  NSEG) g_cur[base + i] = p;
        p += c[i];
    }
}

// ---------------- scatter rows by segment ------------------------------------
__global__ void k_scatter() {
    int i = blockIdx.x * blockDim.x + threadIdx.x;
    int s = g_seg[i];
    int pos = atomicAdd(&g_cur[s], 1);
    g_rows[pos] = i;
}

// ---------------- bf16 hi/lo conversions -------------------------------------
__global__ void k_convx(const float* __restrict__ x) {
    int i = blockIdx.x * blockDim.x + threadIdx.x;   // float4 index
    float4 v = ((const float4*)x)[i];
    __nv_bfloat16 h0 = __float2bfloat16(v.x), h1 = __float2bfloat16(v.y);
    __nv_bfloat16 h2 = __float2bfloat16(v.z), h3 = __float2bfloat16(v.w);
    __nv_bfloat16 l0 = __float2bfloat16(v.x - __bfloat162float(h0));
    __nv_bfloat16 l1 = __float2bfloat16(v.y - __bfloat162float(h1));
    __nv_bfloat16 l2 = __float2bfloat16(v.z - __bfloat162float(h2));
    __nv_bfloat16 l3 = __float2bfloat16(v.w - __bfloat162float(h3));
    __nv_bfloat162 hh0(h0, h1), hh1(h2, h3), ll0(l0, l1), ll1(l2, l3);
    uint2 hp, lp;
    hp.x = *(uint32_t*)&hh0; hp.y = *(uint32_t*)&hh1;
    lp.x = *(uint32_t*)&ll0; lp.y = *(uint32_t*)&ll1;
    ((uint2*)g_xhi)[i] = hp;
    ((uint2*)g_xlo)[i] = lp;
}
__global__ void k_convw(const float* __restrict__ W1, const float* __restrict__ W2,
                        const float* __restrict__ b1, const float* __restrict__ b2) {
    int i = blockIdx.x * blockDim.x + threadIdx.x;   // float4 index over 512x2048
    int e = i * 4;
    int row = e >> 11;
    int col = e & 2047;
    const float* src = (row < 256) ? (W1 + (size_t)row * D_ + col)
                                   : (W2 + (size_t)(row - 256) * D_ + col);
    float4 v = *(const float4*)src;
    __nv_bfloat16 h0 = __float2bfloat16(v.x), h1 = __float2bfloat16(v.y);
    __nv_bfloat16 h2 = __float2bfloat16(v.z), h3 = __float2bfloat16(v.w);
    __nv_bfloat16 l0 = __float2bfloat16(v.x - __bfloat162float(h0));
    __nv_bfloat16 l1 = __float2bfloat16(v.y - __bfloat162float(h1));
    __nv_bfloat16 l2 = __float2bfloat16(v.z - __bfloat162float(h2));
    __nv_bfloat16 l3 = __float2bfloat16(v.w - __bfloat162float(h3));
    __nv_bfloat162 hh0(h0, h1), hh1(h2, h3), ll0(l0, l1), ll1(l2, l3);
    uint2 hp, lp;
    hp.x = *(uint32_t*)&hh0; hp.y = *(uint32_t*)&hh1;
    lp.x = *(uint32_t*)&ll0; lp.y = *(uint32_t*)&ll1;
    ((uint2*)g_bhi)[i] = hp;
    ((uint2*)g_blo)[i] = lp;
    if (blockIdx.x == 0 && threadIdx.x < P_)
        g_bias[threadIdx.x] = b1[threadIdx.x] + b2[threadIdx.x];
}

// ---------------- mma.sync GEMM: [out | y2] = x' @ [W1;W2]'^T ----------------
// CTA 128x128, BK=32, 256 thr, 4-stage cp.async pipeline.
// Stage: A 128x32 bf16 (8KB) + B 128x32 bf16 (8KB) = 16KB; 4 stages = 64KB.
#define STAGE_B 16384
#define SMEM_REQ (NST * STAGE_B)

__device__ __forceinline__ void g_load(int m0, int n0, int kt, uint32_t sbase,
                                       int st, int tid) {
    int term = kt >> 6;                  // 0: hi*hi  1: hi*lo  2: lo*hi
    int k0 = (kt & 63) << 5;             // element offset within K=2048
    const __nv_bfloat16* A = (term < 2) ? g_xhi : g_xlo;
    const __nv_bfloat16* B = (term == 1) ? g_blo : g_bhi;
    const char* gA = (const char*)(A + (size_t)m0 * D_ + k0);
    const char* gB = (const char*)(B + (size_t)n0 * D_ + k0);
    uint32_t sA = sbase + st * STAGE_B;
    uint32_t sB = sA + 8192;
    #pragma unroll
    for (int i = 0; i < 2; i++) {
        int idx = i * 256 + tid;
        int row = idx >> 2, c = idx & 3;
        uint32_t off = swz(row * 64 + c * 16);
        cp16(sA + off, gA + (size_t)row * (D_ * 2) + c * 16);
    }
    #pragma unroll
    for (int i = 0; i < 2; i++) {
        int idx = i * 256 + tid;
        int row = idx >> 2, c = idx & 3;
        uint32_t off = swz(row * 64 + c * 16);
        cp16(sB + off, gB + (size_t)row * (D_ * 2) + c * 16);
    }
}

__global__ void __launch_bounds__(256, 2) k_gemm(float* __restrict__ out) {
    extern __shared__ __align__(128) char smem[];
    uint32_t sbase = smem_u32(smem);
    int tid = threadIdx.x, lane = tid & 31, wid = tid >> 5;
    int wm = wid & 1, wn = wid >> 1;               // warp grid 2(M) x 4(N)
    int n0 = blockIdx.x * 128, m0 = blockIdx.y * 128;

    float d[4][4][4];
    #pragma unroll
    for (int i = 0; i < 4; i++)
        #pragma unroll
        for (int j = 0; j < 4; j++)
            #pragma unroll
            for (int k = 0; k < 4; k++) d[i][j][k] = 0.0f;

    // prologue: stages 0..2
    g_load(m0, n0, 0, sbase, 0, tid); CP_COMMIT();
    g_load(m0, n0, 1, sbase, 1, tid); CP_COMMIT();
    g_load(m0, n0, 2, sbase, 2, tid); CP_COMMIT();

    // precomputed ldmatrix intra-tile offsets (per lane)
    uint32_t aoff[2], boff[2];
    #pragma unroll
    for (int s = 0; s < 2; s++) {
        int arow = wm * 64 + (lane & 15);
        int acol = s * 32 + (lane >> 4) * 16;
        aoff[s] = swz(arow * 64 + acol);
        int brow = wn * 32 + ((lane >> 4) & 1) * 8 + (lane & 7);
        int bcol = s * 32 + ((lane >> 3) & 1) * 16;
        boff[s] = swz(brow * 64 + bcol);
    }

    for (int kt = 0; kt < KT_TOT; kt++) {
        CP_WAIT2();
        __syncthreads();
        if (kt + 3 < KT_TOT)
            g_load(m0, n0, kt + 3, sbase, (kt + 3) & (NST - 1), tid);
        CP_COMMIT();

        uint32_t sA = sbase + (kt & (NST - 1)) * STAGE_B;
        uint32_t sB = sA + 8192;
        #pragma unroll
        for (int s = 0; s < 2; s++) {
            uint32_t a[4][4], b[4][2];
            #pragma unroll
            for (int f = 0; f < 4; f++)
                ldm4(sA + f * 16 * 64 + aoff[s], a[f][0], a[f][1], a[f][2], a[f][3]);
            #pragma unroll
            for (int p = 0; p < 2; p++)
                ldm4(sB + p * 16 * 64 + boff[s],
                     b[2 * p][0], b[2 * p][1], b[2 * p + 1][0], b[2 * p + 1][1]);
            #pragma unroll
            for (int mf = 0; mf < 4; mf++)
                #pragma unroll
                for (int nf = 0; nf < 4; nf++)
                    mma16816(d[mf][nf], a[mf], b[nf]);
        }
    }
    CP_WAIT0();

    // epilogue: n0 in {0,128} -> out, {256,384} -> g_y2
    float* dst;
    int coloff;
    if (n0 < 256) { dst = out;  coloff = n0; }
    else          { dst = g_y2; coloff = n0 - 256; }
    #pragma unroll
    for (int mf = 0; mf < 4; mf++) {
        #pragma unroll
        for (int nf = 0; nf < 4; nf++) {
            int r = m0 + wm * 64 + mf * 16 + (lane >> 2);
            int c = coloff + wn * 32 + nf * 8 + (lane & 3) * 2;
            float2 v0 = make_float2(d[mf][nf][0], d[mf][nf][1]);
            float2 v1 = make_float2(d[mf][nf][2], d[mf][nf][3]);
            *(float2*)(dst + (size_t)r * P_ + c)       = v0;
            *(float2*)(dst + (size_t)(r + 8) * P_ + c) = v1;
        }
    }
}

// ---------------- per-batch column sums of y2 --------------------------------
__global__ void k_sumb() {
    int b = blockIdx.x, h = blockIdx.y;
    int col = h * 128 + threadIdx.x;
    int r0 = g_bstart[b], r1 = g_bstart[b + 1];
    float acc = 0.0f;
    int r = r0;
    for (; r + 4 <= r1; r += 4) {
        float a0 = g_y2[(size_t)(r + 0) * P_ + col];
        float a1 = g_y2[(size_t)(r + 1) * P_ + col];
        float a2 = g_y2[(size_t)(r + 2) * P_ + col];
        float a3 = g_y2[(size_t)(r + 3) * P_ + col];
        acc += (a0 + a1) + (a2 + a3);
    }
    for (; r < r1; r++) acc += g_y2[(size_t)r * P_ + col];
    g_sum_b2[b * P_ + col] = acc;
}

// ---------------- per-(batch,label) column sums of y2 ------------------------
__global__ void k_segsumy() {
    int b = blockIdx.x, h = blockIdx.y, lg = blockIdx.z;
    int col = h * 128 + threadIdx.x;
    for (int j = 0; j < 25; j++) {
        int s = b * NL + lg * 25 + j;
        int i0 = g_off[s], i1 = g_off[s + 1];
        float acc = 0.0f;
        int i = i0;
        for (; i + 2 <= i1; i += 2) {
            float a0 = g_y2[(size_t)g_rows[i]     * P_ + col];
            float a1 = g_y2[(size_t)g_rows[i + 1] * P_ + col];
            acc += a0 + a1;
        }
        if (i < i1) acc += g_y2[(size_t)g_rows[i] * P_ + col];
        g_sum_bl2[(size_t)s * P_ + col] = acc;
    }
}

// ---------------- per-segment output addend ----------------------------------
__global__ void k_minv() {
    int s = blockIdx.x, t = threadIdx.x;
    int b = s / NL;
    int cb = g_bstart[b + 1] - g_bstart[b];
    int d = cb - (g_off[s + 1] - g_off[s]);
    float inv = (d > 0) ? (1.0f / (float)d) : 0.0f;
    float m = (g_sum_b2[b * P_ + t] - g_sum_bl2[(size_t)s * P_ + t]) * inv;
    g_M[(size_t)s * P_ + t] = m + g_bias[t];
}

// ---------------- final gather-add -------------------------------------------
__global__ void k_fixup(float* __restrict__ out) {
    int r = blockIdx.x, t = threadIdx.x;
    int s = g_seg[r];
    out[(size_t)r * P_ + t] += g_M[(size_t)s * P_ + t];
}

// ---------------- launch -----------------------------------------------------
extern "C" void kernel_launch(void* const* d_in, const int* in_sizes, int n_in,
                              void* d_out, int out_size) {
    const float* x     = (const float*)d_in[0];
    const int*   label = (const int*)  d_in[1];
    const int*   lb    = (const int*)  d_in[2];
    const float* W1_w  = (const float*)d_in[3];
    const float* W1_b  = (const float*)d_in[4];
    const float* W2_w  = (const float*)d_in[5];
    const float* W2_b  = (const float*)d_in[6];
    float* out = (float*)d_out;

    cudaFuncSetAttribute(k_gemm, cudaFuncAttributeMaxDynamicSharedMemorySize, SMEM_REQ);

    k_detect<<<1, 256>>>(label, lb);
    k_prep<<<N_ / 256, 256>>>(label, lb);
    k_scan<<<1, 1024>>>();
    k_scatter<<<N_ / 256, 256>>>();
    k_convx<<<(N_ * D_ / 4) / 256, 256>>>(x);
    k_convw<<<(512 * D_ / 4) / 256, 256>>>(W1_w, W2_w, W1_b, W2_b);
    k_gemm<<<dim3(4, 128), 256, SMEM_REQ>>>(out);
    k_sumb<<<dim3(NB, 2), 128>>>();
    k_segsumy<<<dim3(NB, 2, 4), 128>>>();
    k_minv<<<NSEG, 256>>>();
    k_fixup<<<N_, 256>>>(out);
}

// round 5
// speedup vs baseline: 2.3740x; 1.2112x over previous
#include <cuda_runtime.h>
#include <cuda_bf16.h>
#include <cstdint>

#define N_   16384
#define D_   2048
#define P_   256
#define NB   32
#define NL   100
#define NSEG (NB*NL)
#define KT_TOT 64       // K tiles of 32 over K=2048 (terms fused per tile)
#define NST    3        // pipeline stages

// ---------------- scratch globals (no allocations allowed) -------------------
__device__ __nv_bfloat16 g_xhi[N_ * D_];
__device__ __nv_bfloat16 g_xlo[N_ * D_];
__device__ __nv_bfloat16 g_bhi[512 * D_];   // [W1;W2] hi
__device__ __nv_bfloat16 g_blo[512 * D_];   // [W1;W2] lo
__device__ float g_y2[N_ * P_];             // x @ W2^T
__device__ float g_sum_bl2[NSEG * P_];
__device__ float g_sum_b2 [NB   * P_];
__device__ float g_M[NSEG * P_];
__device__ float g_bias[P_];
__device__ int   g_cnt[NSEG];
__device__ int   g_off[NSEG + 1];
__device__ int   g_cur[NSEG];
__device__ int   g_rows[N_];
__device__ int   g_seg[N_];
__device__ int   g_bstart[NB + 1];
__device__ int   g_is64;

// ---------------- PTX helpers ------------------------------------------------
__device__ __forceinline__ uint32_t smem_u32(const void* p) {
    uint32_t a;
    asm("{ .reg .u64 t; cvta.to.shared.u64 t, %1; cvt.u32.u64 %0, t; }" : "=r"(a) : "l"(p));
    return a;
}
__device__ __forceinline__ void cp16(uint32_t dst, const void* src) {
    asm volatile("cp.async.cg.shared.global [%0], [%1], 16;" :: "r"(dst), "l"(src));
}
#define CP_COMMIT() asm volatile("cp.async.commit_group;" ::: "memory")
#define CP_WAIT1()  asm volatile("cp.async.wait_group 1;"  ::: "memory")
#define CP_WAIT0()  asm volatile("cp.async.wait_group 0;"  ::: "memory")

__device__ __forceinline__ uint32_t swz(uint32_t o) {   // 64B-row swizzle
    return o ^ ((o >> 3) & 0x30);
}
__device__ __forceinline__ void ldm4(uint32_t addr, uint32_t& r0, uint32_t& r1,
                                     uint32_t& r2, uint32_t& r3) {
    asm volatile("ldmatrix.sync.aligned.m8n8.x4.shared.b16 {%0,%1,%2,%3}, [%4];"
                 : "=r"(r0), "=r"(r1), "=r"(r2), "=r"(r3) : "r"(addr));
}
__device__ __forceinline__ void mma16816(float* d, const uint32_t* a,
                                         const uint32_t* b) {
    asm volatile(
        "mma.sync.aligned.m16n8k16.row.col.f32.bf16.bf16.f32 "
        "{%0,%1,%2,%3}, {%4,%5,%6,%7}, {%8,%9}, {%0,%1,%2,%3};"
        : "+f"(d[0]), "+f"(d[1]), "+f"(d[2]), "+f"(d[3])
        : "r"(a[0]), "r"(a[1]), "r"(a[2]), "r"(a[3]), "r"(b[0]), "r"(b[1]));
}

// ---------------- dtype detection + count zeroing ----------------------------
__global__ void k_detect(const int* label, const int* lb) {
    __shared__ int nz_la, nz_lb;
    int t = threadIdx.x;
    if (t == 0) { nz_la = 0; nz_lb = 0; }
    __syncthreads();
    if (t < 64) {
        int w = 2 * (t * 128) + 1;
        if (label[w] != 0) atomicOr(&nz_la, 1);
        if (lb[w]    != 0) atomicOr(&nz_lb, 1);
    }
    __syncthreads();
    if (t == 0) g_is64 = (nz_la ? 0 : 1) | (nz_lb ? 0 : 2);
    for (int i = t; i < NSEG; i += blockDim.x) g_cnt[i] = 0;
}
__device__ __forceinline__ int ld_idx(const int* p, int i, bool is64) {
    return is64 ? p[2 * i] : p[i];
}

// ---------------- seg ids, counts, batch boundaries --------------------------
__global__ void k_prep(const int* label, const int* lb) {
    bool la64 = (g_is64 & 1) != 0, lb64 = (g_is64 & 2) != 0;
    int i = blockIdx.x * blockDim.x + threadIdx.x;
    if (i < N_) {
        int la = ld_idx(label, i, la64);
        int b  = ld_idx(lb,    i, lb64);
        int s  = b * NL + la;
        g_seg[i] = s;
        atomicAdd(&g_cnt[s], 1);
    }
    if (blockIdx.x == 0 && threadIdx.x <= NB) {
        int target = threadIdx.x;
        int lo = 0, hi = N_;
        while (lo < hi) {
            int mid = (lo + hi) >> 1;
            if (ld_idx(lb, mid, lb64) < target) lo = mid + 1; else hi = mid;
        }
        g_bstart[target] = lo;
    }
}

// ---------------- prefix scan over seg counts --------------------------------
__global__ void k_scan() {
    __shared__ int sh[1024];
    int t = threadIdx.x;
    int base = t * 4;
    int c[4];
    #pragma unroll
    for (int i = 0; i < 4; i++) c[i] = (base + i < NSEG) ? g_cnt[base + i] : 0;
    int tot = c[0] + c[1] + c[2] + c[3];
    sh[t] = tot;
    __syncthreads();
    int run = tot;
    for (int d = 1; d < 1024; d <<= 1) {
        int v = (t >= d) ? sh[t - d] : 0;
        __syncthreads();
        run += v; sh[t] = run;
        __syncthreads();
    }
    int excl = (t > 0) ? sh[t - 1] : 0;
    int p = excl;
    #pragma unroll
    for (int i = 0; i < 4; i++) {
        if (base + i <= NSEG) g_off[base + i] = p;
        if (base + i <  NSEG) g_cur[base + i] = p;
        p += c[i];
    }
}

// ---------------- scatter rows by segment ------------------------------------
__global__ void k_scatter() {
    int i = blockIdx.x * blockDim.x + threadIdx.x;
    int s = g_seg[i];
    int pos = atomicAdd(&g_cur[s], 1);
    g_rows[pos] = i;
}

// ---------------- bf16 hi/lo conversions -------------------------------------
__global__ void k_convx(const float* __restrict__ x) {
    int i = blockIdx.x * blockDim.x + threadIdx.x;   // float4 index
    float4 v = ((const float4*)x)[i];
    __nv_bfloat16 h0 = __float2bfloat16(v.x), h1 = __float2bfloat16(v.y);
    __nv_bfloat16 h2 = __float2bfloat16(v.z), h3 = __float2bfloat16(v.w);
    __nv_bfloat16 l0 = __float2bfloat16(v.x - __bfloat162float(h0));
    __nv_bfloat16 l1 = __float2bfloat16(v.y - __bfloat162float(h1));
    __nv_bfloat16 l2 = __float2bfloat16(v.z - __bfloat162float(h2));
    __nv_bfloat16 l3 = __float2bfloat16(v.w - __bfloat162float(h3));
    __nv_bfloat162 hh0(h0, h1), hh1(h2, h3), ll0(l0, l1), ll1(l2, l3);
    uint2 hp, lp;
    hp.x = *(uint32_t*)&hh0; hp.y = *(uint32_t*)&hh1;
    lp.x = *(uint32_t*)&ll0; lp.y = *(uint32_t*)&ll1;
    ((uint2*)g_xhi)[i] = hp;
    ((uint2*)g_xlo)[i] = lp;
}
__global__ void k_convw(const float* __restrict__ W1, const float* __restrict__ W2,
                        const float* __restrict__ b1, const float* __restrict__ b2) {
    int i = blockIdx.x * blockDim.x + threadIdx.x;   // float4 index over 512x2048
    int e = i * 4;
    int row = e >> 11;
    int col = e & 2047;
    const float* src = (row < 256) ? (W1 + (size_t)row * D_ + col)
                                   : (W2 + (size_t)(row - 256) * D_ + col);
    float4 v = *(const float4*)src;
    __nv_bfloat16 h0 = __float2bfloat16(v.x), h1 = __float2bfloat16(v.y);
    __nv_bfloat16 h2 = __float2bfloat16(v.z), h3 = __float2bfloat16(v.w);
    __nv_bfloat16 l0 = __float2bfloat16(v.x - __bfloat162float(h0));
    __nv_bfloat16 l1 = __float2bfloat16(v.y - __bfloat162float(h1));
    __nv_bfloat16 l2 = __float2bfloat16(v.z - __bfloat162float(h2));
    __nv_bfloat16 l3 = __float2bfloat16(v.w - __bfloat162float(h3));
    __nv_bfloat162 hh0(h0, h1), hh1(h2, h3), ll0(l0, l1), ll1(l2, l3);
    uint2 hp, lp;
    hp.x = *(uint32_t*)&hh0; hp.y = *(uint32_t*)&hh1;
    lp.x = *(uint32_t*)&ll0; lp.y = *(uint32_t*)&ll1;
    ((uint2*)g_bhi)[i] = hp;
    ((uint2*)g_blo)[i] = lp;
    if (blockIdx.x == 0 && threadIdx.x < P_)
        g_bias[threadIdx.x] = b1[threadIdx.x] + b2[threadIdx.x];
}

// ---------------- mma.sync GEMM: [out | y2] = x' @ [W1;W2]'^T ----------------
// CTA 128x128, BK=32, 256 thr, 3-stage cp.async pipeline, terms fused per tile.
// Stage blocks: A_hi 8K | A_lo 8K | B_hi 8K | B_lo 8K = 32KB.
// n-blocks 0,1 (W1 -> out): 3 passes (hi*hi, hi*lo, lo*hi).
// n-blocks 2,3 (W2 -> y2): hi*hi only, loads A_hi/B_hi only.
#define STAGE_B 32768
#define SMEM_REQ (NST * STAGE_B)

__device__ __forceinline__ void ld_block(uint32_t sdst, const char* gsrc, int tid) {
    #pragma unroll
    for (int i = 0; i < 2; i++) {
        int idx = i * 256 + tid;
        int row = idx >> 2, c = idx & 3;
        uint32_t off = swz(row * 64 + c * 16);
        cp16(sdst + off, gsrc + (size_t)row * (D_ * 2) + c * 16);
    }
}

__device__ __forceinline__ void g_load(int m0, int n0, int kt, uint32_t sbase,
                                       int st, int tid, bool w1) {
    int k0 = kt << 5;
    uint32_t sg = sbase + st * STAGE_B;
    const char* gAh = (const char*)(g_xhi + (size_t)m0 * D_ + k0);
    const char* gBh = (const char*)(g_bhi + (size_t)n0 * D_ + k0);
    ld_block(sg,         gAh, tid);
    ld_block(sg + 16384, gBh, tid);
    if (w1) {
        const char* gAl = (const char*)(g_xlo + (size_t)m0 * D_ + k0);
        const char* gBl = (const char*)(g_blo + (size_t)n0 * D_ + k0);
        ld_block(sg + 8192,  gAl, tid);
        ld_block(sg + 24576, gBl, tid);
    }
}

__global__ void __launch_bounds__(256, 2) k_gemm(float* __restrict__ out) {
    extern __shared__ __align__(128) char smem[];
    uint32_t sbase = smem_u32(smem);
    int tid = threadIdx.x, lane = tid & 31, wid = tid >> 5;
    int wm = wid & 1, wn = wid >> 1;               // warp grid 2(M) x 4(N)
    int n0 = blockIdx.x * 128, m0 = blockIdx.y * 128;
    bool w1 = (n0 < 256);

    float d[4][4][4];
    #pragma unroll
    for (int i = 0; i < 4; i++)
        #pragma unroll
        for (int j = 0; j < 4; j++)
            #pragma unroll
            for (int k = 0; k < 4; k++) d[i][j][k] = 0.0f;

    // prologue: stages 0,1
    g_load(m0, n0, 0, sbase, 0, tid, w1); CP_COMMIT();
    g_load(m0, n0, 1, sbase, 1, tid, w1); CP_COMMIT();

    // precomputed ldmatrix intra-block offsets (per lane)
    uint32_t aoff[2], boff[2];
    #pragma unroll
    for (int s = 0; s < 2; s++) {
        int arow = wm * 64 + (lane & 15);
        int acol = s * 32 + (lane >> 4) * 16;
        aoff[s] = swz(arow * 64 + acol);
        int brow = wn * 32 + ((lane >> 4) & 1) * 8 + (lane & 7);
        int bcol = s * 32 + ((lane >> 3) & 1) * 16;
        boff[s] = swz(brow * 64 + bcol);
    }

    for (int kt = 0; kt < KT_TOT; kt++) {
        CP_WAIT1();
        __syncthreads();
        if (kt + 2 < KT_TOT)
            g_load(m0, n0, kt + 2, sbase, (kt + 2) % NST, tid, w1);
        CP_COMMIT();

        uint32_t sAh = sbase + (kt % NST) * STAGE_B;
        uint32_t sAl = sAh + 8192;
        uint32_t sBh = sAh + 16384;
        uint32_t sBl = sAh + 24576;
        #pragma unroll
        for (int s = 0; s < 2; s++) {
            uint32_t a[4][4], bh[4][2];
            #pragma unroll
            for (int f = 0; f < 4; f++)
                ldm4(sAh + f * 1024 + aoff[s], a[f][0], a[f][1], a[f][2], a[f][3]);
            #pragma unroll
            for (int p = 0; p < 2; p++)
                ldm4(sBh + p * 1024 + boff[s],
                     bh[2 * p][0], bh[2 * p][1], bh[2 * p + 1][0], bh[2 * p + 1][1]);
            #pragma unroll
            for (int mf = 0; mf < 4; mf++)
                #pragma unroll
                for (int nf = 0; nf < 4; nf++)
                    mma16816(d[mf][nf], a[mf], bh[nf]);
            if (w1) {
                uint32_t bl[4][2];
                #pragma unroll
                for (int p = 0; p < 2; p++)
                    ldm4(sBl + p * 1024 + boff[s],
                         bl[2 * p][0], bl[2 * p][1], bl[2 * p + 1][0], bl[2 * p + 1][1]);
                #pragma unroll
                for (int mf = 0; mf < 4; mf++)
                    #pragma unroll
                    for (int nf = 0; nf < 4; nf++)
                        mma16816(d[mf][nf], a[mf], bl[nf]);
                // overwrite a with A_lo, reuse bh (B_hi)
                #pragma unroll
                for (int f = 0; f < 4; f++)
                    ldm4(sAl + f * 1024 + aoff[s], a[f][0], a[f][1], a[f][2], a[f][3]);
                #pragma unroll
                for (int mf = 0; mf < 4; mf++)
                    #pragma unroll
                    for (int nf = 0; nf < 4; nf++)
                        mma16816(d[mf][nf], a[mf], bh[nf]);
            }
        }
    }
    CP_WAIT0();

    // epilogue: n0 in {0,128} -> out, {256,384} -> g_y2
    float* dst;
    int coloff;
    if (w1) { dst = out;  coloff = n0; }
    else    { dst = g_y2; coloff = n0 - 256; }
    #pragma unroll
    for (int mf = 0; mf < 4; mf++) {
        #pragma unroll
        for (int nf = 0; nf < 4; nf++) {
            int r = m0 + wm * 64 + mf * 16 + (lane >> 2);
            int c = coloff + wn * 32 + nf * 8 + (lane & 3) * 2;
            float2 v0 = make_float2(d[mf][nf][0], d[mf][nf][1]);
            float2 v1 = make_float2(d[mf][nf][2], d[mf][nf][3]);
            *(float2*)(dst + (size_t)r * P_ + c)       = v0;
            *(float2*)(dst + (size_t)(r + 8) * P_ + c) = v1;
        }
    }
}

// ---------------- per-batch column sums of y2 --------------------------------
__global__ void k_sumb() {
    int b = blockIdx.x, h = blockIdx.y;
    int col = h * 128 + threadIdx.x;
    int r0 = g_bstart[b], r1 = g_bstart[b + 1];
    float acc = 0.0f;
    int r = r0;
    for (; r + 4 <= r1; r += 4) {
        float a0 = g_y2[(size_t)(r + 0) * P_ + col];
        float a1 = g_y2[(size_t)(r + 1) * P_ + col];
        float a2 = g_y2[(size_t)(r + 2) * P_ + col];
        float a3 = g_y2[(size_t)(r + 3) * P_ + col];
        acc += (a0 + a1) + (a2 + a3);
    }
    for (; r < r1; r++) acc += g_y2[(size_t)r * P_ + col];
    g_sum_b2[b * P_ + col] = acc;
}

// ---------------- per-(batch,label) column sums of y2 ------------------------
__global__ void k_segsumy() {
    int b = blockIdx.x, h = blockIdx.y, lg = blockIdx.z;
    int col = h * 128 + threadIdx.x;
    for (int j = 0; j < 25; j++) {
        int s = b * NL + lg * 25 + j;
        int i0 = g_off[s], i1 = g_off[s + 1];
        float acc = 0.0f;
        int i = i0;
        for (; i + 2 <= i1; i += 2) {
            float a0 = g_y2[(size_t)g_rows[i]     * P_ + col];
            float a1 = g_y2[(size_t)g_rows[i + 1] * P_ + col];
            acc += a0 + a1;
        }
        if (i < i1) acc += g_y2[(size_t)g_rows[i] * P_ + col];
        g_sum_bl2[(size_t)s * P_ + col] = acc;
    }
}

// ---------------- per-segment output addend ----------------------------------
__global__ void k_minv() {
    int s = blockIdx.x, t = threadIdx.x;
    int b = s / NL;
    int cb = g_bstart[b + 1] - g_bstart[b];
    int d = cb - (g_off[s + 1] - g_off[s]);
    float inv = (d > 0) ? (1.0f / (float)d) : 0.0f;
    float m = (g_sum_b2[b * P_ + t] - g_sum_bl2[(size_t)s * P_ + t]) * inv;
    g_M[(size_t)s * P_ + t] = m + g_bias[t];
}

// ---------------- final gather-add -------------------------------------------
__global__ void k_fixup(float* __restrict__ out) {
    int r = blockIdx.x, t = threadIdx.x;
    int s = g_seg[r];
    out[(size_t)r * P_ + t] += g_M[(size_t)s * P_ + t];
}

// ---------------- launch -----------------------------------------------------
extern "C" void kernel_launch(void* const* d_in, const int* in_sizes, int n_in,
                              void* d_out, int out_size) {
    const float* x     = (const float*)d_in[0];
    const int*   label = (const int*)  d_in[1];
    const int*   lb    = (const int*)  d_in[2];
    const float* W1_w  = (const float*)d_in[3];
    const float* W1_b  = (const float*)d_in[4];
    const float* W2_w  = (const float*)d_in[5];
    const float* W2_b  = (const float*)d_in[6];
    float* out = (float*)d_out;

    cudaFuncSetAttribute(k_gemm, cudaFuncAttributeMaxDynamicSharedMemorySize, SMEM_REQ);

    k_detect<<<1, 256>>>(label, lb);
    k_prep<<<N_ / 256, 256>>>(label, lb);
    k_scan<<<1, 1024>>>();
    k_scatter<<<N_ / 256, 256>>>();
    k_convx<<<(N_ * D_ / 4) / 256, 256>>>(x);
    k_convw<<<(512 * D_ / 4) / 256, 256>>>(W1_w, W2_w, W1_b, W2_b);
    k_gemm<<<dim3(4, 128), 256, SMEM_REQ>>>(out);
    k_sumb<<<dim3(NB, 2), 128>>>();
    k_segsumy<<<dim3(NB, 2, 4), 128>>>();
    k_minv<<<NSEG, 256>>>();
    k_fixup<<<N_, 256>>>(out);
}

// round 6
// speedup vs baseline: 2.5539x; 1.0758x over previous
#include <cuda_runtime.h>
#include <cuda_bf16.h>
#include <cstdint>

#define N_   16384
#define D_   2048
#define P_   256
#define NB   32
#define NL   100
#define NSEG (NB*NL)
#define KT_TOT 64       // K tiles of 32 over K=2048 (terms fused per tile)
#define NST    3        // pipeline stages

// ---------------- scratch globals (no allocations allowed) -------------------
__device__ __nv_bfloat16 g_bhi[512 * D_];   // [W1;W2] hi
__device__ __nv_bfloat16 g_blo[512 * D_];   // [W1;W2] lo
__device__ float g_y2[N_ * P_];             // x @ W2^T
__device__ float g_sum_bl2[NSEG * P_];
__device__ float g_sum_b2 [NB   * P_];
__device__ float g_M[NSEG * P_];
__device__ float g_bias[P_];
__device__ int   g_cnt[NSEG];
__device__ int   g_off[NSEG + 1];
__device__ int   g_cur[NSEG];
__device__ int   g_rows[N_];
__device__ int   g_seg[N_];
__device__ int   g_bstart[NB + 1];
__device__ int   g_is64;

// ---------------- PTX helpers ------------------------------------------------
__device__ __forceinline__ uint32_t smem_u32(const void* p) {
    uint32_t a;
    asm("{ .reg .u64 t; cvta.to.shared.u64 t, %1; cvt.u32.u64 %0, t; }" : "=r"(a) : "l"(p));
    return a;
}
__device__ __forceinline__ void cp16(uint32_t dst, const void* src) {
    asm volatile("cp.async.cg.shared.global [%0], [%1], 16;" :: "r"(dst), "l"(src));
}
#define CP_COMMIT() asm volatile("cp.async.commit_group;" ::: "memory")
#define CP_WAIT1()  asm volatile("cp.async.wait_group 1;"  ::: "memory")
#define CP_WAIT0()  asm volatile("cp.async.wait_group 0;"  ::: "memory")

__device__ __forceinline__ uint32_t swz(uint32_t o) {   // 64B-row swizzle
    return o ^ ((o >> 3) & 0x30);
}
__device__ __forceinline__ void ldm4(uint32_t addr, uint32_t& r0, uint32_t& r1,
                                     uint32_t& r2, uint32_t& r3) {
    asm volatile("ldmatrix.sync.aligned.m8n8.x4.shared.b16 {%0,%1,%2,%3}, [%4];"
                 : "=r"(r0), "=r"(r1), "=r"(r2), "=r"(r3) : "r"(addr));
}
__device__ __forceinline__ void mma16816(float* d, const uint32_t* a,
                                         const uint32_t* b) {
    asm volatile(
        "mma.sync.aligned.m16n8k16.row.col.f32.bf16.bf16.f32 "
        "{%0,%1,%2,%3}, {%4,%5,%6,%7}, {%8,%9}, {%0,%1,%2,%3};"
        : "+f"(d[0]), "+f"(d[1]), "+f"(d[2]), "+f"(d[3])
        : "r"(a[0]), "r"(a[1]), "r"(a[2]), "r"(a[3]), "r"(b[0]), "r"(b[1]));
}
__device__ __forceinline__ void sts16(uint32_t addr, uint32_t r0, uint32_t r1,
                                      uint32_t r2, uint32_t r3) {
    asm volatile("st.shared.v4.b32 [%0], {%1,%2,%3,%4};"
                 :: "r"(addr), "r"(r0), "r"(r1), "r"(r2), "r"(r3) : "memory");
}

// hi/lo packers: 4 floats -> 2x uint32 (bf16x2) each
__device__ __forceinline__ void pack_hilo(float4 v, uint32_t& h0, uint32_t& h1,
                                          uint32_t& l0, uint32_t& l1) {
    __nv_bfloat16 a = __float2bfloat16(v.x), b = __float2bfloat16(v.y);
    __nv_bfloat16 c = __float2bfloat16(v.z), d = __float2bfloat16(v.w);
    __nv_bfloat16 e = __float2bfloat16(v.x - __bfloat162float(a));
    __nv_bfloat16 f = __float2bfloat16(v.y - __bfloat162float(b));
    __nv_bfloat16 g = __float2bfloat16(v.z - __bfloat162float(c));
    __nv_bfloat16 h = __float2bfloat16(v.w - __bfloat162float(d));
    __nv_bfloat162 hh0(a, b), hh1(c, d), ll0(e, f), ll1(g, h);
    h0 = *(uint32_t*)&hh0; h1 = *(uint32_t*)&hh1;
    l0 = *(uint32_t*)&ll0; l1 = *(uint32_t*)&ll1;
}

// ---------------- dtype detection + count zeroing ----------------------------
__global__ void k_detect(const int* label, const int* lb) {
    __shared__ int nz_la, nz_lb;
    int t = threadIdx.x;
    if (t == 0) { nz_la = 0; nz_lb = 0; }
    __syncthreads();
    if (t < 64) {
        int w = 2 * (t * 128) + 1;
        if (label[w] != 0) atomicOr(&nz_la, 1);
        if (lb[w]    != 0) atomicOr(&nz_lb, 1);
    }
    __syncthreads();
    if (t == 0) g_is64 = (nz_la ? 0 : 1) | (nz_lb ? 0 : 2);
    for (int i = t; i < NSEG; i += blockDim.x) g_cnt[i] = 0;
}
__device__ __forceinline__ int ld_idx(const int* p, int i, bool is64) {
    return is64 ? p[2 * i] : p[i];
}

// ---------------- seg ids, counts, batch boundaries --------------------------
__global__ void k_prep(const int* label, const int* lb) {
    bool la64 = (g_is64 & 1) != 0, lb64 = (g_is64 & 2) != 0;
    int i = blockIdx.x * blockDim.x + threadIdx.x;
    if (i < N_) {
        int la = ld_idx(label, i, la64);
        int b  = ld_idx(lb,    i, lb64);
        int s  = b * NL + la;
        g_seg[i] = s;
        atomicAdd(&g_cnt[s], 1);
    }
    if (blockIdx.x == 0 && threadIdx.x <= NB) {
        int target = threadIdx.x;
        int lo = 0, hi = N_;
        while (lo < hi) {
            int mid = (lo + hi) >> 1;
            if (ld_idx(lb, mid, lb64) < target) lo = mid + 1; else hi = mid;
        }
        g_bstart[target] = lo;
    }
}

// ---------------- prefix scan over seg counts --------------------------------
__global__ void k_scan() {
    __shared__ int sh[1024];
    int t = threadIdx.x;
    int base = t * 4;
    int c[4];
    #pragma unroll
    for (int i = 0; i < 4; i++) c[i] = (base + i < NSEG) ? g_cnt[base + i] : 0;
    int tot = c[0] + c[1] + c[2] + c[3];
    sh[t] = tot;
    __syncthreads();
    int run = tot;
    for (int d = 1; d < 1024; d <<= 1) {
        int v = (t >= d) ? sh[t - d] : 0;
        __syncthreads();
        run += v; sh[t] = run;
        __syncthreads();
    }
    int excl = (t > 0) ? sh[t - 1] : 0;
    int p = excl;
    #pragma unroll
    for (int i = 0; i < 4; i++) {
        if (base + i <= NSEG) g_off[base + i] = p;
        if (base + i <  NSEG) g_cur[base + i] = p;
        p += c[i];
    }
}

// ---------------- scatter rows by segment ------------------------------------
__global__ void k_scatter() {
    int i = blockIdx.x * blockDim.x + threadIdx.x;
    int s = g_seg[i];
    int pos = atomicAdd(&g_cur[s], 1);
    g_rows[pos] = i;
}

// ---------------- weight hi/lo conversion ------------------------------------
__global__ void k_convw(const float* __restrict__ W1, const float* __restrict__ W2,
                        const float* __restrict__ b1, const float* __restrict__ b2) {
    int i = blockIdx.x * blockDim.x + threadIdx.x;   // float4 index over 512x2048
    int e = i * 4;
    int row = e >> 11;
    int col = e & 2047;
    const float* src = (row < 256) ? (W1 + (size_t)row * D_ + col)
                                   : (W2 + (size_t)(row - 256) * D_ + col);
    float4 v = *(const float4*)src;
    uint32_t h0, h1, l0, l1;
    pack_hilo(v, h0, h1, l0, l1);
    uint2 hp = make_uint2(h0, h1), lp = make_uint2(l0, l1);
    ((uint2*)g_bhi)[i] = hp;
    ((uint2*)g_blo)[i] = lp;
    if (blockIdx.x == 0 && threadIdx.x < P_)
        g_bias[threadIdx.x] = b1[threadIdx.x] + b2[threadIdx.x];
}

// ---------------- mma.sync GEMM: [out | y2] = x @ [W1;W2]^T ------------------
// CTA 128x128, BK=32, 256 thr, 3-stage pipeline.
// A: fp32 x LDG -> regs -> bf16 hi/lo STS (fused conversion, no g_x copies).
// B: cp.async bf16 (hi, and lo for W1 CTAs).
// Stage blocks: A_hi 8K | A_lo 8K | B_hi 8K | B_lo 8K = 32KB.
#define STAGE_B 32768
#define SMEM_REQ (NST * STAGE_B)

__device__ __forceinline__ void ldgA(const float* __restrict__ x, int m0, int kt,
                                     int tid, float4* areg) {
    // thread t: row = t>>1, cols (t&1)*16 .. +15  (64B contiguous)
    int row = tid >> 1, h = tid & 1;
    const float4* p = (const float4*)(x + (size_t)(m0 + row) * D_ + (kt << 5) + h * 16);
    areg[0] = p[0]; areg[1] = p[1]; areg[2] = p[2]; areg[3] = p[3];
}

__device__ __forceinline__ void stsA(uint32_t sg, int tid, const float4* areg, bool w1) {
    int row = tid >> 1, h = tid & 1;
    uint32_t hi0[2], hi1[2], lo0[2], lo1[2];
    pack_hilo(areg[0], hi0[0], hi0[1], lo0[0], lo0[1]);
    pack_hilo(areg[1], hi1[0], hi1[1], lo1[0], lo1[1]);
    uint32_t hi2[2], hi3[2], lo2[2], lo3[2];
    pack_hilo(areg[2], hi2[0], hi2[1], lo2[0], lo2[1]);
    pack_hilo(areg[3], hi3[0], hi3[1], lo3[0], lo3[1]);
    uint32_t o0 = swz(row * 64 + h * 32);
    uint32_t o1 = swz(row * 64 + h * 32 + 16);
    sts16(sg + o0, hi0[0], hi0[1], hi1[0], hi1[1]);
    sts16(sg + o1, hi2[0], hi2[1], hi3[0], hi3[1]);
    if (w1) {
        sts16(sg + 8192 + o0, lo0[0], lo0[1], lo1[0], lo1[1]);
        sts16(sg + 8192 + o1, lo2[0], lo2[1], lo3[0], lo3[1]);
    }
}

__device__ __forceinline__ void ldB(int n0, int kt, uint32_t sg, int tid, bool w1) {
    int k0 = kt << 5;
    const char* gBh = (const char*)(g_bhi + (size_t)n0 * D_ + k0);
    #pragma unroll
    for (int i = 0; i < 2; i++) {
        int idx = i * 256 + tid;
        int row = idx >> 2, c = idx & 3;
        uint32_t off = swz(row * 64 + c * 16);
        cp16(sg + 16384 + off, gBh + (size_t)row * (D_ * 2) + c * 16);
    }
    if (w1) {
        const char* gBl = (const char*)(g_blo + (size_t)n0 * D_ + k0);
        #pragma unroll
        for (int i = 0; i < 2; i++) {
            int idx = i * 256 + tid;
            int row = idx >> 2, c = idx & 3;
            uint32_t off = swz(row * 64 + c * 16);
            cp16(sg + 24576 + off, gBl + (size_t)row * (D_ * 2) + c * 16);
        }
    }
}

__global__ void __launch_bounds__(256, 2) k_gemm(const float* __restrict__ x,
                                                 float* __restrict__ out) {
    extern __shared__ __align__(128) char smem[];
    uint32_t sbase = smem_u32(smem);
    int tid = threadIdx.x, lane = tid & 31, wid = tid >> 5;
    int wm = wid & 1, wn = wid >> 1;               // warp grid 2(M) x 4(N)
    int n0 = blockIdx.x * 128, m0 = blockIdx.y * 128;
    bool w1 = (n0 < 256);

    float d[4][4][4];
    #pragma unroll
    for (int i = 0; i < 4; i++)
        #pragma unroll
        for (int j = 0; j < 4; j++)
            #pragma unroll
            for (int k = 0; k < 4; k++) d[i][j][k] = 0.0f;

    float4 areg[4];
    // prologue: A(0) -> stage0, A(1) held in regs; B(0), B(1) in flight
    ldgA(x, m0, 0, tid, areg);
    stsA(sbase, tid, areg, w1);
    ldB(n0, 0, sbase, tid, w1); CP_COMMIT();
    ldgA(x, m0, 1, tid, areg);
    ldB(n0, 1, sbase + STAGE_B, tid, w1); CP_COMMIT();

    // precomputed ldmatrix intra-block offsets (per lane)
    uint32_t aoff[2], boff[2];
    #pragma unroll
    for (int s = 0; s < 2; s++) {
        int arow = wm * 64 + (lane & 15);
        int acol = s * 32 + (lane >> 4) * 16;
        aoff[s] = swz(arow * 64 + acol);
        int brow = wn * 32 + ((lane >> 4) & 1) * 8 + (lane & 7);
        int bcol = s * 32 + ((lane >> 3) & 1) * 16;
        boff[s] = swz(brow * 64 + bcol);
    }

    for (int kt = 0; kt < KT_TOT; kt++) {
        CP_WAIT1();
        __syncthreads();
        // store A(kt+1) from regs; fetch A(kt+2) + B(kt+2)
        if (kt + 1 < KT_TOT)
            stsA(sbase + ((kt + 1) % NST) * STAGE_B, tid, areg, w1);
        if (kt + 2 < KT_TOT) {
            ldgA(x, m0, kt + 2, tid, areg);
            ldB(n0, kt + 2, sbase + ((kt + 2) % NST) * STAGE_B, tid, w1);
        }
        CP_COMMIT();

        uint32_t sAh = sbase + (kt % NST) * STAGE_B;
        uint32_t sAl = sAh + 8192;
        uint32_t sBh = sAh + 16384;
        uint32_t sBl = sAh + 24576;
        #pragma unroll
        for (int s = 0; s < 2; s++) {
            uint32_t a[4][4], bh[4][2];
            #pragma unroll
            for (int f = 0; f < 4; f++)
                ldm4(sAh + f * 1024 + aoff[s], a[f][0], a[f][1], a[f][2], a[f][3]);
            #pragma unroll
            for (int p = 0; p < 2; p++)
                ldm4(sBh + p * 1024 + boff[s],
                     bh[2 * p][0], bh[2 * p][1], bh[2 * p + 1][0], bh[2 * p + 1][1]);
            #pragma unroll
            for (int mf = 0; mf < 4; mf++)
                #pragma unroll
                for (int nf = 0; nf < 4; nf++)
                    mma16816(d[mf][nf], a[mf], bh[nf]);
            if (w1) {
                uint32_t bl[4][2];
                #pragma unroll
                for (int p = 0; p < 2; p++)
                    ldm4(sBl + p * 1024 + boff[s],
                         bl[2 * p][0], bl[2 * p][1], bl[2 * p + 1][0], bl[2 * p + 1][1]);
                #pragma unroll
                for (int mf = 0; mf < 4; mf++)
                    #pragma unroll
                    for (int nf = 0; nf < 4; nf++)
                        mma16816(d[mf][nf], a[mf], bl[nf]);
                // overwrite a with A_lo, reuse bh (B_hi)
                #pragma unroll
                for (int f = 0; f < 4; f++)
                    ldm4(sAl + f * 1024 + aoff[s], a[f][0], a[f][1], a[f][2], a[f][3]);
                #pragma unroll
                for (int mf = 0; mf < 4; mf++)
                    #pragma unroll
                    for (int nf = 0; nf < 4; nf++)
                        mma16816(d[mf][nf], a[mf], bh[nf]);
            }
        }
    }
    CP_WAIT0();

    // epilogue: n0 in {0,128} -> out, {256,384} -> g_y2
    float* dst;
    int coloff;
    if (w1) { dst = out;  coloff = n0; }
    else    { dst = g_y2; coloff = n0 - 256; }
    #pragma unroll
    for (int mf = 0; mf < 4; mf++) {
        #pragma unroll
        for (int nf = 0; nf < 4; nf++) {
            int r = m0 + wm * 64 + mf * 16 + (lane >> 2);
            int c = coloff + wn * 32 + nf * 8 + (lane & 3) * 2;
            float2 v0 = make_float2(d[mf][nf][0], d[mf][nf][1]);
            float2 v1 = make_float2(d[mf][nf][2], d[mf][nf][3]);
            *(float2*)(dst + (size_t)r * P_ + c)       = v0;
            *(float2*)(dst + (size_t)(r + 8) * P_ + c) = v1;
        }
    }
}

// ---------------- per-(batch,label) column sums of y2 ------------------------
__global__ void k_segsumy() {
    int b = blockIdx.x, h = blockIdx.y, lg = blockIdx.z;
    int col = h * 128 + threadIdx.x;
    for (int j = 0; j < 25; j++) {
        int s = b * NL + lg * 25 + j;
        int i0 = g_off[s], i1 = g_off[s + 1];
        float acc = 0.0f;
        int i = i0;
        for (; i + 2 <= i1; i += 2) {
            float a0 = g_y2[(size_t)g_rows[i]     * P_ + col];
            float a1 = g_y2[(size_t)g_rows[i + 1] * P_ + col];
            acc += a0 + a1;
        }
        if (i < i1) acc += g_y2[(size_t)g_rows[i] * P_ + col];
        g_sum_bl2[(size_t)s * P_ + col] = acc;
    }
}

// ---------------- per-batch sums from per-seg sums ---------------------------
__global__ void k_sumb() {
    int b = blockIdx.x, h = blockIdx.y;
    int col = h * 128 + threadIdx.x;
    const float* base = g_sum_bl2 + (size_t)(b * NL) * P_ + col;
    float acc = 0.0f;
    #pragma unroll 4
    for (int l = 0; l < NL; l++) acc += base[(size_t)l * P_];
    g_sum_b2[b * P_ + col] = acc;
}

// ---------------- per-segment output addend ----------------------------------
__global__ void k_minv() {
    int s = blockIdx.x, t = threadIdx.x;
    int b = s / NL;
    int cb = g_bstart[b + 1] - g_bstart[b];
    int d = cb - (g_off[s + 1] - g_off[s]);
    float inv = (d > 0) ? (1.0f / (float)d) : 0.0f;
    float m = (g_sum_b2[b * P_ + t] - g_sum_bl2[(size_t)s * P_ + t]) * inv;
    g_M[(size_t)s * P_ + t] = m + g_bias[t];
}

// ---------------- final gather-add -------------------------------------------
__global__ void k_fixup(float* __restrict__ out) {
    int r = blockIdx.x, t = threadIdx.x;
    int s = g_seg[r];
    out[(size_t)r * P_ + t] += g_M[(size_t)s * P_ + t];
}

// ---------------- launch -----------------------------------------------------
extern "C" void kernel_launch(void* const* d_in, const int* in_sizes, int n_in,
                              void* d_out, int out_size) {
    const float* x     = (const float*)d_in[0];
    const int*   label = (const int*)  d_in[1];
    const int*   lb    = (const int*)  d_in[2];
    const float* W1_w  = (const float*)d_in[3];
    const float* W1_b  = (const float*)d_in[4];
    const float* W2_w  = (const float*)d_in[5];
    const float* W2_b  = (const float*)d_in[6];
    float* out = (float*)d_out;

    cudaFuncSetAttribute(k_gemm, cudaFuncAttributeMaxDynamicSharedMemorySize, SMEM_REQ);

    // order chosen so k_gemm is the 4th launch (ncu captures slot 4)
    k_convw<<<(512 * D_ / 4) / 256, 256>>>(W1_w, W2_w, W1_b, W2_b);
    k_detect<<<1, 256>>>(label, lb);
    k_prep<<<N_ / 256, 256>>>(label, lb);
    k_gemm<<<dim3(4, 128), 256, SMEM_REQ>>>(x, out);
    k_scan<<<1, 1024>>>();
    k_scatter<<<N_ / 256, 256>>>();
    k_segsumy<<<dim3(NB, 2, 4), 128>>>();
    k_sumb<<<dim3(NB, 2), 128>>>();
    k_minv<<<NSEG, 256>>>();
    k_fixup<<<N_, 256>>>(out);
}

// round 7
// speedup vs baseline: 2.7609x; 1.0810x over previous
#include <cuda_runtime.h>
#include <cuda_bf16.h>
#include <cstdint>

#define N_   16384
#define D_   2048
#define P_   256
#define NB   32
#define NL   100
#define NSEG (NB*NL)
#define NST  3          // pipeline stages

// ---------------- scratch globals (no allocations allowed) -------------------
__device__ __nv_bfloat16 g_bhi[512 * D_];   // [W1;W2] hi
__device__ __nv_bfloat16 g_blo[512 * D_];   // [W1;W2] lo
__device__ float g_sumx[NSEG * D_];         // exact fp32 segsum of x   26MB
__device__ float g_mpart[4 * NSEG * P_];    // K-split partials of segsum@W2^T
__device__ float g_sum_bl2[NSEG * P_];
__device__ float g_sum_b2 [NB   * P_];
__device__ float g_M[NSEG * P_];
__device__ float g_bias[P_];
__device__ int   g_cnt[NSEG];
__device__ int   g_seg[N_];
__device__ int   g_bstart[NB + 1];
__device__ int   g_is64;

// ---------------- PTX helpers ------------------------------------------------
__device__ __forceinline__ uint32_t smem_u32(const void* p) {
    uint32_t a;
    asm("{ .reg .u64 t; cvta.to.shared.u64 t, %1; cvt.u32.u64 %0, t; }" : "=r"(a) : "l"(p));
    return a;
}
__device__ __forceinline__ void cp16(uint32_t dst, const void* src) {
    asm volatile("cp.async.cg.shared.global [%0], [%1], 16;" :: "r"(dst), "l"(src));
}
#define CP_COMMIT() asm volatile("cp.async.commit_group;" ::: "memory")
#define CP_WAIT1()  asm volatile("cp.async.wait_group 1;"  ::: "memory")
#define CP_WAIT0()  asm volatile("cp.async.wait_group 0;"  ::: "memory")

__device__ __forceinline__ uint32_t swz(uint32_t o) {   // 64B-row swizzle
    return o ^ ((o >> 3) & 0x30);
}
__device__ __forceinline__ void ldm4(uint32_t addr, uint32_t& r0, uint32_t& r1,
                                     uint32_t& r2, uint32_t& r3) {
    asm volatile("ldmatrix.sync.aligned.m8n8.x4.shared.b16 {%0,%1,%2,%3}, [%4];"
                 : "=r"(r0), "=r"(r1), "=r"(r2), "=r"(r3) : "r"(addr));
}
__device__ __forceinline__ void mma16816(float* d, const uint32_t* a,
                                         const uint32_t* b) {
    asm volatile(
        "mma.sync.aligned.m16n8k16.row.col.f32.bf16.bf16.f32 "
        "{%0,%1,%2,%3}, {%4,%5,%6,%7}, {%8,%9}, {%0,%1,%2,%3};"
        : "+f"(d[0]), "+f"(d[1]), "+f"(d[2]), "+f"(d[3])
        : "r"(a[0]), "r"(a[1]), "r"(a[2]), "r"(a[3]), "r"(b[0]), "r"(b[1]));
}
__device__ __forceinline__ void sts16(uint32_t addr, uint32_t r0, uint32_t r1,
                                      uint32_t r2, uint32_t r3) {
    asm volatile("st.shared.v4.b32 [%0], {%1,%2,%3,%4};"
                 :: "r"(addr), "r"(r0), "r"(r1), "r"(r2), "r"(r3) : "memory");
}

// 4 floats -> hi bf16x2 pair + lo bf16x2 pair
__device__ __forceinline__ void pack_hilo(float4 v, uint32_t& h0, uint32_t& h1,
                                          uint32_t& l0, uint32_t& l1) {
    __nv_bfloat16 a = __float2bfloat16(v.x), b = __float2bfloat16(v.y);
    __nv_bfloat16 c = __float2bfloat16(v.z), d = __float2bfloat16(v.w);
    __nv_bfloat16 e = __float2bfloat16(v.x - __bfloat162float(a));
    __nv_bfloat16 f = __float2bfloat16(v.y - __bfloat162float(b));
    __nv_bfloat16 g = __float2bfloat16(v.z - __bfloat162float(c));
    __nv_bfloat16 h = __float2bfloat16(v.w - __bfloat162float(d));
    __nv_bfloat162 hh0(a, b), hh1(c, d), ll0(e, f), ll1(g, h);
    h0 = *(uint32_t*)&hh0; h1 = *(uint32_t*)&hh1;
    l0 = *(uint32_t*)&ll0; l1 = *(uint32_t*)&ll1;
}

// ---------------- dtype detection + count zeroing ----------------------------
__global__ void k_detect(const int* label, const int* lb) {
    __shared__ int nz_la, nz_lb;
    int t = threadIdx.x;
    if (t == 0) { nz_la = 0; nz_lb = 0; }
    __syncthreads();
    if (t < 64) {
        int w = 2 * (t * 128) + 1;
        if (label[w] != 0) atomicOr(&nz_la, 1);
        if (lb[w]    != 0) atomicOr(&nz_lb, 1);
    }
    __syncthreads();
    if (t == 0) g_is64 = (nz_la ? 0 : 1) | (nz_lb ? 0 : 2);
    for (int i = t; i < NSEG; i += blockDim.x) g_cnt[i] = 0;
}
__device__ __forceinline__ int ld_idx(const int* p, int i, bool is64) {
    return is64 ? p[2 * i] : p[i];
}

// ---------------- seg ids, counts, batch boundaries --------------------------
__global__ void k_prep(const int* label, const int* lb) {
    bool la64 = (g_is64 & 1) != 0, lb64 = (g_is64 & 2) != 0;
    int i = blockIdx.x * blockDim.x + threadIdx.x;
    if (i < N_) {
        int la = ld_idx(label, i, la64);
        int b  = ld_idx(lb,    i, lb64);
        int s  = b * NL + la;
        g_seg[i] = s;
        atomicAdd(&g_cnt[s], 1);
    }
    if (blockIdx.x == 0 && threadIdx.x <= NB) {
        int target = threadIdx.x;
        int lo = 0, hi = N_;
        while (lo < hi) {
            int mid = (lo + hi) >> 1;
            if (ld_idx(lb, mid, lb64) < target) lo = mid + 1; else hi = mid;
        }
        g_bstart[target] = lo;
    }
}

// ---------------- weight hi/lo conversion ------------------------------------
__global__ void k_convw(const float* __restrict__ W1, const float* __restrict__ W2,
                        const float* __restrict__ b1, const float* __restrict__ b2) {
    int i = blockIdx.x * blockDim.x + threadIdx.x;   // float4 index over 512x2048
    int e = i * 4;
    int row = e >> 11;
    int col = e & 2047;
    const float* src = (row < 256) ? (W1 + (size_t)row * D_ + col)
                                   : (W2 + (size_t)(row - 256) * D_ + col);
    float4 v = *(const float4*)src;
    uint32_t h0, h1, l0, l1;
    pack_hilo(v, h0, h1, l0, l1);
    ((uint2*)g_bhi)[i] = make_uint2(h0, h1);
    ((uint2*)g_blo)[i] = make_uint2(l0, l1);
    if (blockIdx.x == 0 && threadIdx.x < P_)
        g_bias[threadIdx.x] = b1[threadIdx.x] + b2[threadIdx.x];
}

// ---------------- exact fp32 segment sums of x -------------------------------
// grid (D/64 chunks, NB batches); smem acc 100 labels x 64 cols.
__global__ void k_segsum(const float* __restrict__ x) {
    __shared__ float acc[NL * 64];      // 25.6 KB
    int b  = blockIdx.y;
    int c0 = blockIdx.x * 64;
    int t  = threadIdx.x;
    for (int i = t; i < NL * 64; i += 256) acc[i] = 0.0f;
    __syncthreads();
    int r0 = g_bstart[b], r1 = g_bstart[b + 1];
    int col = t & 63, rs = t >> 6;
    for (int r = r0 + rs; r < r1; r += 4) {
        int lab = g_seg[r] - b * NL;
        atomicAdd(&acc[lab * 64 + col], x[(size_t)r * D_ + c0 + col]);
    }
    __syncthreads();
    for (int i = t; i < NL * 64; i += 256) {
        int l = i >> 6, c = i & 63;
        g_sumx[(size_t)(b * NL + l) * D_ + c0 + c] = acc[i];
    }
}

// ---------------- shared 3-term bf16 GEMM core -------------------------------
// CTA tile 64(M) x 128(N), BK=32, 256 threads, warp grid 2x4 (tile 32x32).
// A: fp32 LDG -> regs -> bf16 hi/lo STS.  B: cp.async from g_bhi/g_blo.
// Stage: A_hi 4K | A_lo 4K | B_hi 8K | B_lo 8K = 24KB.  NST=3 -> 72KB.
#define STAGE_B 24576
#define SMEM_REQ (NST * STAGE_B)

__device__ __forceinline__ void ldgA(const float* __restrict__ Arows, int kt,
                                     int tid, float4* areg) {
    int row = tid >> 2, h = tid & 3;                 // 4 thr/row, 8 floats each
    const float4* p = (const float4*)(Arows + (size_t)row * D_ + (kt << 5) + h * 8);
    areg[0] = p[0]; areg[1] = p[1];
}
__device__ __forceinline__ void stsA(uint32_t sg, int tid, const float4* areg) {
    int row = tid >> 2, h = tid & 3;
    uint32_t h0a, h1a, l0a, l1a, h0b, h1b, l0b, l1b;
    pack_hilo(areg[0], h0a, h1a, l0a, l1a);
    pack_hilo(areg[1], h0b, h1b, l0b, l1b);
    uint32_t o = swz(row * 64 + h * 16);
    sts16(sg + o,        h0a, h1a, h0b, h1b);        // A_hi
    sts16(sg + 4096 + o, l0a, l1a, l0b, l1b);        // A_lo
}
__device__ __forceinline__ void ldB(const __nv_bfloat16* Bh, const __nv_bfloat16* Bl,
                                    int kt, uint32_t sg, int tid) {
    int k0 = kt << 5;
    const char* gBh = (const char*)(Bh + k0);
    const char* gBl = (const char*)(Bl + k0);
    #pragma unroll
    for (int i = 0; i < 2; i++) {
        int idx = i * 256 + tid;
        int row = idx >> 2, c = idx & 3;
        uint32_t off = swz(row * 64 + c * 16);
        cp16(sg + 8192  + off, gBh + (size_t)row * (D_ * 2) + c * 16);
        cp16(sg + 16384 + off, gBl + (size_t)row * (D_ * 2) + c * 16);
    }
}

__device__ __forceinline__ void gemm_core(uint32_t sbase,
                                          const float* __restrict__ Arows,
                                          const __nv_bfloat16* __restrict__ Bh,
                                          const __nv_bfloat16* __restrict__ Bl,
                                          float* __restrict__ dst, int ktn) {
    int tid = threadIdx.x, lane = tid & 31, wid = tid >> 5;
    int wm = wid & 1, wn = wid >> 1;                 // warp grid 2(M) x 4(N)

    float d[2][4][4];
    #pragma unroll
    for (int i = 0; i < 2; i++)
        #pragma unroll
        for (int j = 0; j < 4; j++)
            #pragma unroll
            for (int k = 0; k < 4; k++) d[i][j][k] = 0.0f;

    float4 areg[2];
    ldgA(Arows, 0, tid, areg);
    stsA(sbase, tid, areg);
    ldB(Bh, Bl, 0, sbase, tid); CP_COMMIT();
    ldgA(Arows, 1, tid, areg);
    ldB(Bh, Bl, 1, sbase + STAGE_B, tid); CP_COMMIT();

    uint32_t aoff[2], boff[2];
    #pragma unroll
    for (int s = 0; s < 2; s++) {
        int arow = wm * 32 + (lane & 15);
        int acol = s * 32 + (lane >> 4) * 16;
        aoff[s] = swz(arow * 64 + acol);
        int brow = wn * 32 + ((lane >> 4) & 1) * 8 + (lane & 7);
        int bcol = s * 32 + ((lane >> 3) & 1) * 16;
        boff[s] = swz(brow * 64 + bcol);
    }

    for (int kt = 0; kt < ktn; kt++) {
        CP_WAIT1();
        __syncthreads();
        if (kt + 1 < ktn)
            stsA(sbase + ((kt + 1) % NST) * STAGE_B, tid, areg);
        if (kt + 2 < ktn) {
            ldgA(Arows, kt + 2, tid, areg);
            ldB(Bh, Bl, kt + 2, sbase + ((kt + 2) % NST) * STAGE_B, tid);
        }
        CP_COMMIT();

        uint32_t sAh = sbase + (kt % NST) * STAGE_B;
        uint32_t sAl = sAh + 4096;
        uint32_t sBh = sAh + 8192;
        uint32_t sBl = sAh + 16384;
        #pragma unroll
        for (int s = 0; s < 2; s++) {
            uint32_t a[2][4], bh[4][2], bl[4][2];
            #pragma unroll
            for (int f = 0; f < 2; f++)
                ldm4(sAh + f * 1024 + aoff[s], a[f][0], a[f][1], a[f][2], a[f][3]);
            #pragma unroll
            for (int p = 0; p < 2; p++)
                ldm4(sBh + p * 1024 + boff[s],
                     bh[2 * p][0], bh[2 * p][1], bh[2 * p + 1][0], bh[2 * p + 1][1]);
            #pragma unroll
            for (int mf = 0; mf < 2; mf++)
                #pragma unroll
                for (int nf = 0; nf < 4; nf++)
                    mma16816(d[mf][nf], a[mf], bh[nf]);
            #pragma unroll
            for (int p = 0; p < 2; p++)
                ldm4(sBl + p * 1024 + boff[s],
                     bl[2 * p][0], bl[2 * p][1], bl[2 * p + 1][0], bl[2 * p + 1][1]);
            #pragma unroll
            for (int mf = 0; mf < 2; mf++)
                #pragma unroll
                for (int nf = 0; nf < 4; nf++)
                    mma16816(d[mf][nf], a[mf], bl[nf]);
            #pragma unroll
            for (int f = 0; f < 2; f++)
                ldm4(sAl + f * 1024 + aoff[s], a[f][0], a[f][1], a[f][2], a[f][3]);
            #pragma unroll
            for (int mf = 0; mf < 2; mf++)
                #pragma unroll
                for (int nf = 0; nf < 4; nf++)
                    mma16816(d[mf][nf], a[mf], bh[nf]);
        }
    }
    CP_WAIT0();

    #pragma unroll
    for (int mf = 0; mf < 2; mf++) {
        #pragma unroll
        for (int nf = 0; nf < 4; nf++) {
            int r = wm * 32 + mf * 16 + (lane >> 2);
            int c = wn * 32 + nf * 8 + (lane & 3) * 2;
            *(float2*)(dst + (size_t)r * P_ + c)
                = make_float2(d[mf][nf][0], d[mf][nf][1]);
            *(float2*)(dst + (size_t)(r + 8) * P_ + c)
                = make_float2(d[mf][nf][2], d[mf][nf][3]);
        }
    }
}

// ---------------- main GEMM: out = x @ W1^T (3-term bf16) --------------------
__global__ void __launch_bounds__(256, 3) k_gemm(const float* __restrict__ x,
                                                 float* __restrict__ out) {
    extern __shared__ __align__(128) char smem[];
    uint32_t sbase = smem_u32(smem);
    int n0 = blockIdx.x * 128, m0 = blockIdx.y * 64;
    gemm_core(sbase,
              x + (size_t)m0 * D_,
              g_bhi + (size_t)n0 * D_,
              g_blo + (size_t)n0 * D_,
              out + (size_t)m0 * P_ + n0, 64);
}

// ---------------- mean GEMM: g_mpart[ks] = segsum_x @ W2^T (K-split 4) -------
__global__ void __launch_bounds__(256, 3) k_mgemm() {
    extern __shared__ __align__(128) char smem[];
    uint32_t sbase = smem_u32(smem);
    int n0 = blockIdx.x * 128, m0 = blockIdx.y * 64, ks = blockIdx.z;
    gemm_core(sbase,
              g_sumx + (size_t)m0 * D_ + ks * 512,
              g_bhi + (size_t)(256 + n0) * D_ + ks * 512,
              g_blo + (size_t)(256 + n0) * D_ + ks * 512,
              g_mpart + (size_t)ks * NSEG * P_ + (size_t)m0 * P_ + n0, 16);
}

// ---------------- reduce K-split parts ---------------------------------------
__global__ void k_mred() {
    int i = blockIdx.x * blockDim.x + threadIdx.x;   // over NSEG*P_
    float s = g_mpart[i] + g_mpart[NSEG * P_ + i]
            + g_mpart[2 * NSEG * P_ + i] + g_mpart[3 * NSEG * P_ + i];
    g_sum_bl2[i] = s;
}

// ---------------- per-batch sums from per-seg sums ---------------------------
__global__ void k_sumb() {
    int b = blockIdx.x, h = blockIdx.y;
    int col = h * 128 + threadIdx.x;
    const float* base = g_sum_bl2 + (size_t)(b * NL) * P_ + col;
    float acc = 0.0f;
    #pragma unroll 4
    for (int l = 0; l < NL; l++) acc += base[(size_t)l * P_];
    g_sum_b2[b * P_ + col] = acc;
}

// ---------------- per-segment output addend ----------------------------------
__global__ void k_minv() {
    int s = blockIdx.x, t = threadIdx.x;
    int b = s / NL;
    int cb = g_bstart[b + 1] - g_bstart[b];
    int d = cb - g_cnt[s];
    float inv = (d > 0) ? (1.0f / (float)d) : 0.0f;
    float m = (g_sum_b2[b * P_ + t] - g_sum_bl2[(size_t)s * P_ + t]) * inv;
    g_M[(size_t)s * P_ + t] = m + g_bias[t];
}

// ---------------- final gather-add -------------------------------------------
__global__ void k_fixup(float* __restrict__ out) {
    int r = blockIdx.x, t = threadIdx.x;
    int s = g_seg[r];
    out[(size_t)r * P_ + t] += g_M[(size_t)s * P_ + t];
}

// ---------------- launch -----------------------------------------------------
extern "C" void kernel_launch(void* const* d_in, const int* in_sizes, int n_in,
                              void* d_out, int out_size) {
    const float* x     = (const float*)d_in[0];
    const int*   label = (const int*)  d_in[1];
    const int*   lb    = (const int*)  d_in[2];
    const float* W1_w  = (const float*)d_in[3];
    const float* W1_b  = (const float*)d_in[4];
    const float* W2_w  = (const float*)d_in[5];
    const float* W2_b  = (const float*)d_in[6];
    float* out = (float*)d_out;

    cudaFuncSetAttribute(k_gemm,  cudaFuncAttributeMaxDynamicSharedMemorySize, SMEM_REQ);
    cudaFuncSetAttribute(k_mgemm, cudaFuncAttributeMaxDynamicSharedMemorySize, SMEM_REQ);

    // order chosen so k_gemm is the 4th launch (ncu captures slot 4)
    k_convw<<<(512 * D_ / 4) / 256, 256>>>(W1_w, W2_w, W1_b, W2_b);
    k_detect<<<1, 256>>>(label, lb);
    k_prep<<<N_ / 256, 256>>>(label, lb);
    k_gemm<<<dim3(2, 256), 256, SMEM_REQ>>>(x, out);
    k_segsum<<<dim3(D_ / 64, NB), 256>>>(x);
    k_mgemm<<<dim3(2, NSEG / 64, 4), 256, SMEM_REQ>>>();
    k_mred<<<(NSEG * P_) / 256, 256>>>();
    k_sumb<<<dim3(NB, 2), 128>>>();
    k_minv<<<NSEG, 256>>>();
    k_fixup<<<N_, 256>>>(out);
}